// round 5
// baseline (speedup 1.0000x reference)
#include <cuda_runtime.h>
#include <cstdint>

#define B_ 128
#define I_ 64
#define S_ 2048
#define CLUSTER 8
#define NTHR 256

// scratch: x transposed to [t][b][i]
__device__ float g_xT[(size_t)S_ * B_ * I_];

struct Smem {
  float in[192][8];         // k<64: x_t ; 64..192: h ; rows 0-3 = stream A, 4-7 = B
  float iin[256][8];        // k<128: x_in ; else h_in ; same row split
  float partial[8][64][4];  // gemv k-split partials (per active stream)
  float partialP[8][8][9];  // projection partials [kq][oo][row8]
  float stX[64];            // x_in staging (own slice: 16 jj x 4 row)
  float stHi[64];           // h_in staging
  float stH[64];            // h staging
  unsigned long long mb_iinA, mb_iinB, mb_hA, mb_hB;
};

__device__ __forceinline__ float tanh_ap(float x) {
  float y;
  asm("tanh.approx.f32 %0, %1;" : "=f"(y) : "f"(x));
  return y;
}
__device__ __forceinline__ float sigm_t(float x) {
  return fmaf(0.5f, tanh_ap(0.5f * x), 0.5f);
}
__device__ __forceinline__ void ffma2(unsigned long long& d, unsigned long long a,
                                      unsigned long long b) {
  asm("fma.rn.f32x2 %0, %1, %2, %0;" : "+l"(d) : "l"(a), "l"(b));
}
__device__ __forceinline__ unsigned long long dupf(float w) {
  unsigned long long r;
  asm("mov.b64 %0, {%1, %1};" : "=l"(r) : "f"(w));
  return r;
}
__device__ __forceinline__ uint32_t mapa_u32(uint32_t addr, uint32_t r) {
  uint32_t o;
  asm("mapa.shared::cluster.u32 %0, %1, %2;" : "=r"(o) : "r"(addr), "r"(r));
  return o;
}
__device__ __forceinline__ void stc128(uint32_t addr, float4 v) {
  asm volatile("st.shared::cluster.v4.f32 [%0], {%1,%2,%3,%4};" ::"r"(addr), "f"(v.x),
               "f"(v.y), "f"(v.z), "f"(v.w)
               : "memory");
}
__device__ __forceinline__ void fence_cl() {
  asm volatile("fence.acq_rel.cluster;" ::: "memory");
}
__device__ __forceinline__ void arrive_remote(uint32_t local_mbar, uint32_t r) {
  uint32_t rem = mapa_u32(local_mbar, r);
  asm volatile("mbarrier.arrive.release.cluster.shared::cluster.b64 _, [%0];" ::"r"(rem)
               : "memory");
}
__device__ __forceinline__ void mbar_init(uint32_t mbar, uint32_t count) {
  asm volatile("mbarrier.init.shared.b64 [%0], %1;" ::"r"(mbar), "r"(count) : "memory");
}
__device__ __forceinline__ void wait_parity_cluster(uint32_t mbar, uint32_t parity) {
  asm volatile(
      "{\n\t.reg .pred P1;\n\t"
      "WL_%=:\n\t"
      "mbarrier.try_wait.parity.acquire.cluster.shared::cta.b64 P1, [%0], %1, 0x989680;\n\t"
      "@P1 bra.uni WD_%=;\n\t"
      "bra.uni WL_%=;\n\t"
      "WD_%=:\n\t}" ::"r"(mbar),
      "r"(parity)
      : "memory");
}
__device__ __forceinline__ void cluster_sync_() {
  asm volatile("barrier.cluster.arrive.aligned;" ::: "memory");
  asm volatile("barrier.cluster.wait.aligned;" ::: "memory");
}

__global__ void transpose_x(const float* __restrict__ x) {
  __shared__ float tile[32][33];
  int b = blockIdx.z;
  int i0 = blockIdx.y * 32;
  int t0 = blockIdx.x * 32;
  int tx = threadIdx.x, ty = threadIdx.y;
#pragma unroll
  for (int j = 0; j < 32; j += 8)
    tile[ty + j][tx] = x[(size_t)b * (I_ * S_) + (size_t)(i0 + ty + j) * S_ + t0 + tx];
  __syncthreads();
#pragma unroll
  for (int j = 0; j < 32; j += 8)
    g_xT[(size_t)(t0 + ty + j) * (B_ * I_) + b * I_ + i0 + tx] = tile[tx][ty + j];
}

template <int KB>
__device__ __forceinline__ void gemv_acc(const float (&w)[2][KB], const float* __restrict__ up,
                                         unsigned long long (&acc)[2][2]) {
#pragma unroll
  for (int kk = 0; kk < KB; ++kk) {
    ulonglong2 u = *reinterpret_cast<const ulonglong2*>(up + kk * 8);
#pragma unroll
    for (int cg = 0; cg < 2; ++cg) {
      unsigned long long wp = dupf(w[cg][kk]);
      ffma2(acc[cg][0], wp, u.x);
      ffma2(acc[cg][1], wp, u.y);
    }
  }
}

__global__ void __launch_bounds__(NTHR, 1) __cluster_dims__(CLUSTER, 1, 1)
nlstm_kernel(const float* __restrict__ Wx_out, const float* __restrict__ Wh_out,
             const float* __restrict__ b_out, const float* __restrict__ Wx_in,
             const float* __restrict__ Wh_in, const float* __restrict__ b_in,
             const float* __restrict__ W_lin, const float* __restrict__ b_lin,
             float* __restrict__ out) {
  extern __shared__ __align__(16) char smem_raw[];
  Smem& sm = *reinterpret_cast<Smem*>(smem_raw);
  const int tid = threadIdx.x;
  const int warp = tid >> 5, lane = tid & 31;
  const int rank = blockIdx.x & (CLUSTER - 1);
  const int b0 = (blockIdx.x >> 3) * 8;

  // ---- init smem: h(0)=0, stage x(0) ----
  for (int idx = tid; idx < 128 * 8; idx += NTHR) sm.in[64 + (idx >> 3)][idx & 7] = 0.f;
  for (int idx = tid; idx < 512; idx += NTHR)
    sm.in[idx & 63][idx >> 6] = g_xT[(size_t)(b0 + (idx >> 6)) * I_ + (idx & 63)];
  const uint32_t mbA = (uint32_t)__cvta_generic_to_shared(&sm.mb_iinA);
  const uint32_t mbB = (uint32_t)__cvta_generic_to_shared(&sm.mb_iinB);
  const uint32_t mhA = (uint32_t)__cvta_generic_to_shared(&sm.mb_hA);
  const uint32_t mhB = (uint32_t)__cvta_generic_to_shared(&sm.mb_hB);
  if (tid == 0) {
    mbar_init(mbA, CLUSTER);
    mbar_init(mbB, CLUSTER);
    mbar_init(mhA, CLUSTER);
    mbar_init(mhB, CLUSTER);
  }
  __syncthreads();
  cluster_sync_();

  // ---- register weights: warp = k-split(8), lane covers cols (lane, lane+32) ----
  float wOx[2][8], wOh[2][16], wI[2][32];
#pragma unroll
  for (int cg = 0; cg < 2; ++cg) {
    int c = cg * 32 + lane;
    int gcol = ((c >> 4) << 7) + (rank << 4) + (c & 15);
#pragma unroll
    for (int kk = 0; kk < 8; ++kk) wOx[cg][kk] = Wx_out[(warp * 8 + kk) * 512 + gcol];
#pragma unroll
    for (int kk = 0; kk < 16; ++kk) wOh[cg][kk] = Wh_out[(warp * 16 + kk) * 512 + gcol];
#pragma unroll
    for (int kk = 0; kk < 32; ++kk) {
      int k = warp * 32 + kk;
      wI[cg][kk] = (k < 128) ? Wx_in[k * 512 + gcol] : Wh_in[(k - 128) * 512 + gcol];
    }
  }
  // proj weights: thread = (kq=warp, oo=(tid>>2)&7, rp=tid&3)
  float wlin[16];
  {
    int oo = (tid >> 2) & 7;
#pragma unroll
    for (int kk = 0; kk < 16; ++kk)
      wlin[kk] = W_lin[(rank * 8 + oo) * 128 + warp * 16 + kk];
  }
  // bias regs for state threads ((tid&3)==0): n=tid>>2 -> (jj,row)
  float boR[4], biR[4];
  {
    int jj = (tid >> 2) >> 2;
#pragma unroll
    for (int g = 0; g < 4; ++g) {
      int gcol = g * 128 + rank * 16 + jj;
      boR[g] = b_out[gcol];
      biR[g] = b_in[gcol];
    }
  }
  const float blinR = b_lin[rank * 8 + (((tid >> 2) >> 3) & 7)];

  const uint32_t iin_base = (uint32_t)__cvta_generic_to_shared(&sm.iin[0][0]);
  const uint32_t in_base = (uint32_t)__cvta_generic_to_shared(&sm.in[0][0]);

  float cA = 0.f, cnA = 0.f, oA = 0.f;
  float cB = 0.f, cnB = 0.f, oB = 0.f;
  float2 xpf = make_float2(0.f, 0.f);

  const int n_st = tid >> 2, jj_st = (tid >> 2) >> 2, row_st = (tid >> 2) & 3;
  const bool is_state = (tid & 3) == 0;
  const bool is_pred = (tid & 3) == 1;
  const int m_pr = tid >> 2, oo_pr = ((tid >> 2) >> 3) & 7, row_pr = (tid >> 2) & 7;
  (void)n_st;

#pragma unroll 1
  for (int t = 0; t < S_; ++t) {
    const uint32_t pw = (uint32_t)(t & 1);
    const uint32_t ph = (uint32_t)((t - 1) & 1);

    // ================= Ph1 =================
    if (t > 0) {  // h_B(t-1) broadcast: warp w -> rank w
      if (lane < 16) {
        float4 v = *reinterpret_cast<const float4*>(&sm.stH[lane * 4]);
        uint32_t dst = in_base + (uint32_t)(64 + rank * 16 + lane) * 32 + 16;
        stc128(mapa_u32(dst, warp), v);
      }
      __syncwarp();
      if (lane == 0) {
        fence_cl();
        arrive_remote(mhB, warp);
      }
    }
    if (t + 1 < S_)
      xpf = *reinterpret_cast<const float2*>(
          &g_xT[(size_t)(t + 1) * (B_ * I_) + b0 * I_ + tid * 2]);
    {
      unsigned long long acc[2][2] = {{0ull, 0ull}, {0ull, 0ull}};
      gemv_acc<8>(wOx, &sm.in[warp * 8][0], acc);  // A x-part
      if (t > 0) wait_parity_cluster(mhA, ph);
      gemv_acc<16>(wOh, &sm.in[64 + warp * 16][0], acc);  // A h-part
#pragma unroll
      for (int cg = 0; cg < 2; ++cg)
        *reinterpret_cast<ulonglong2*>(&sm.partial[warp][cg * 32 + lane][0]) =
            make_ulonglong2(acc[cg][0], acc[cg][1]);
    }
    if (t > 0) {  // proj-A partial for h(t-1), rows 0-3
      int rp = tid & 3, oo = (tid >> 2) & 7;
      float pa = 0.f;
#pragma unroll
      for (int kk = 0; kk < 16; ++kk) pa += wlin[kk] * sm.in[64 + warp * 16 + kk][rp];
      sm.partialP[warp][oo][rp] = pa;
    }
    __syncthreads();

    // ================= Ph2: A outer reduce/combine =================
    if (is_state) {
      float s0 = boR[0], s1 = boR[1], s2 = boR[2], s3 = boR[3];
#pragma unroll
      for (int ks = 0; ks < 8; ++ks) {
        s0 += sm.partial[ks][jj_st][row_st];
        s1 += sm.partial[ks][16 + jj_st][row_st];
        s2 += sm.partial[ks][32 + jj_st][row_st];
        s3 += sm.partial[ks][48 + jj_st][row_st];
      }
      float iv = sigm_t(s0), fv = sigm_t(s1);
      oA = sigm_t(s2);
      float gv = tanh_ap(s3);
      sm.stX[jj_st * 4 + row_st] = iv * gv;
      sm.stHi[jj_st * 4 + row_st] = fv * cA;
    }
    __syncthreads();

    // ================= Ph3 =================
    {  // iin_A broadcast
      float4 v = (lane < 16)
                     ? *reinterpret_cast<const float4*>(&sm.stX[lane * 4])
                     : *reinterpret_cast<const float4*>(&sm.stHi[(lane - 16) * 4]);
      uint32_t r = (lane < 16) ? (uint32_t)(rank * 16 + lane)
                               : (uint32_t)(128 + rank * 16 + lane - 16);
      stc128(mapa_u32(iin_base + r * 32, warp), v);
      __syncwarp();
      if (lane == 0) {
        fence_cl();
        arrive_remote(mbA, warp);
      }
    }
    {
      unsigned long long acc[2][2] = {{0ull, 0ull}, {0ull, 0ull}};
      gemv_acc<8>(wOx, &sm.in[warp * 8][4], acc);  // B x-part
      if (t > 0) wait_parity_cluster(mhB, ph);
      gemv_acc<16>(wOh, &sm.in[64 + warp * 16][4], acc);  // B h-part
#pragma unroll
      for (int cg = 0; cg < 2; ++cg)
        *reinterpret_cast<ulonglong2*>(&sm.partial[warp][cg * 32 + lane][0]) =
            make_ulonglong2(acc[cg][0], acc[cg][1]);
    }
    if (t > 0) {  // proj-B partial for h(t-1), rows 4-7
      int rp = (tid & 3) + 4, oo = (tid >> 2) & 7;
      float pa = 0.f;
#pragma unroll
      for (int kk = 0; kk < 16; ++kk) pa += wlin[kk] * sm.in[64 + warp * 16 + kk][rp];
      sm.partialP[warp][oo][rp] = pa;
    }
    __syncthreads();

    // ================= Ph4: B outer reduce/combine =================
    if (is_state) {
      float s0 = boR[0], s1 = boR[1], s2 = boR[2], s3 = boR[3];
#pragma unroll
      for (int ks = 0; ks < 8; ++ks) {
        s0 += sm.partial[ks][jj_st][row_st];
        s1 += sm.partial[ks][16 + jj_st][row_st];
        s2 += sm.partial[ks][32 + jj_st][row_st];
        s3 += sm.partial[ks][48 + jj_st][row_st];
      }
      float iv = sigm_t(s0), fv = sigm_t(s1);
      oB = sigm_t(s2);
      float gv = tanh_ap(s3);
      sm.stX[jj_st * 4 + row_st] = iv * gv;
      sm.stHi[jj_st * 4 + row_st] = fv * cB;
    }
    __syncthreads();

    // ================= Ph5 =================
    {  // iin_B broadcast (rows 4-7 -> byte offset 16)
      float4 v = (lane < 16)
                     ? *reinterpret_cast<const float4*>(&sm.stX[lane * 4])
                     : *reinterpret_cast<const float4*>(&sm.stHi[(lane - 16) * 4]);
      uint32_t r = (lane < 16) ? (uint32_t)(rank * 16 + lane)
                               : (uint32_t)(128 + rank * 16 + lane - 16);
      stc128(mapa_u32(iin_base + r * 32 + 16, warp), v);
      __syncwarp();
      if (lane == 0) {
        fence_cl();
        arrive_remote(mbB, warp);
      }
    }
    wait_parity_cluster(mbA, pw);
    {
      unsigned long long acc[2][2] = {{0ull, 0ull}, {0ull, 0ull}};
      gemv_acc<32>(wI, &sm.iin[warp * 32][0], acc);  // A inner
#pragma unroll
      for (int cg = 0; cg < 2; ++cg)
        *reinterpret_cast<ulonglong2*>(&sm.partial[warp][cg * 32 + lane][0]) =
            make_ulonglong2(acc[cg][0], acc[cg][1]);
    }
    __syncthreads();

    // ================= Ph6: A inner reduce/state | proj reduce t-1 =================
    if (is_state) {
      float s0 = biR[0], s1 = biR[1], s2 = biR[2], s3 = biR[3];
#pragma unroll
      for (int ks = 0; ks < 8; ++ks) {
        s0 += sm.partial[ks][jj_st][row_st];
        s1 += sm.partial[ks][16 + jj_st][row_st];
        s2 += sm.partial[ks][32 + jj_st][row_st];
        s3 += sm.partial[ks][48 + jj_st][row_st];
      }
      float ii = sigm_t(s0), ff = sigm_t(s1), o2 = sigm_t(s2), gg = tanh_ap(s3);
      cnA = ff * cnA + ii * gg;
      cA = o2 * tanh_ap(cnA);
      sm.stH[jj_st * 4 + row_st] = oA * tanh_ap(cA);
    } else if (is_pred && t > 0) {
      float s = blinR;
#pragma unroll
      for (int kq = 0; kq < 8; ++kq) s += sm.partialP[kq][oo_pr][row_pr];
      out[((size_t)(b0 + row_pr) * S_ + (t - 1)) * 64 + rank * 8 + oo_pr] = s;
    }
    __syncthreads();

    // ================= Ph7 =================
    {  // h_A broadcast
      if (lane < 16) {
        float4 v = *reinterpret_cast<const float4*>(&sm.stH[lane * 4]);
        uint32_t dst = in_base + (uint32_t)(64 + rank * 16 + lane) * 32;
        stc128(mapa_u32(dst, warp), v);
      }
      __syncwarp();
      if (lane == 0) {
        fence_cl();
        arrive_remote(mhA, warp);
      }
    }
    wait_parity_cluster(mbB, pw);
    {
      unsigned long long acc[2][2] = {{0ull, 0ull}, {0ull, 0ull}};
      gemv_acc<32>(wI, &sm.iin[warp * 32][4], acc);  // B inner
#pragma unroll
      for (int cg = 0; cg < 2; ++cg)
        *reinterpret_cast<ulonglong2*>(&sm.partial[warp][cg * 32 + lane][0]) =
            make_ulonglong2(acc[cg][0], acc[cg][1]);
    }
    if (t + 1 < S_) {  // stage x(t+1)
      int idx = tid * 2;
      sm.in[idx & 63][idx >> 6] = xpf.x;
      sm.in[(idx + 1) & 63][idx >> 6] = xpf.y;
    }
    __syncthreads();

    // ================= Ph8: B inner reduce/state =================
    if (is_state) {
      float s0 = biR[0], s1 = biR[1], s2 = biR[2], s3 = biR[3];
#pragma unroll
      for (int ks = 0; ks < 8; ++ks) {
        s0 += sm.partial[ks][jj_st][row_st];
        s1 += sm.partial[ks][16 + jj_st][row_st];
        s2 += sm.partial[ks][32 + jj_st][row_st];
        s3 += sm.partial[ks][48 + jj_st][row_st];
      }
      float ii = sigm_t(s0), ff = sigm_t(s1), o2 = sigm_t(s2), gg = tanh_ap(s3);
      cnB = ff * cnB + ii * gg;
      cB = o2 * tanh_ap(cnB);
      sm.stH[jj_st * 4 + row_st] = oB * tanh_ap(cB);
    }
    __syncthreads();
  }

  // ================= epilogue: t = S_-1 projection =================
  {  // h_B(S-1) broadcast
    if (lane < 16) {
      float4 v = *reinterpret_cast<const float4*>(&sm.stH[lane * 4]);
      uint32_t dst = in_base + (uint32_t)(64 + rank * 16 + lane) * 32 + 16;
      stc128(mapa_u32(dst, warp), v);
    }
    __syncwarp();
    if (lane == 0) {
      fence_cl();
      arrive_remote(mhB, warp);
    }
  }
  wait_parity_cluster(mhA, (uint32_t)((S_ - 1) & 1));
  wait_parity_cluster(mhB, (uint32_t)((S_ - 1) & 1));
  {
    int rp = tid & 3, oo = (tid >> 2) & 7;
    float pa = 0.f, pb = 0.f;
#pragma unroll
    for (int kk = 0; kk < 16; ++kk) {
      pa += wlin[kk] * sm.in[64 + warp * 16 + kk][rp];
      pb += wlin[kk] * sm.in[64 + warp * 16 + kk][rp + 4];
    }
    sm.partialP[warp][oo][rp] = pa;
    sm.partialP[warp][oo][rp + 4] = pb;
  }
  __syncthreads();
  if (is_pred) {
    float s = blinR;
#pragma unroll
    for (int kq = 0; kq < 8; ++kq) s += sm.partialP[kq][oo_pr][row_pr];
    out[((size_t)(b0 + row_pr) * S_ + (S_ - 1)) * 64 + rank * 8 + oo_pr] = s;
  }
}

extern "C" void kernel_launch(void* const* d_in, const int* in_sizes, int n_in,
                              void* d_out, int out_size) {
  (void)in_sizes;
  (void)n_in;
  (void)out_size;
  cudaFuncSetAttribute(nlstm_kernel, cudaFuncAttributeMaxDynamicSharedMemorySize,
                       (int)sizeof(Smem));
  transpose_x<<<dim3(S_ / 32, I_ / 32, B_), dim3(32, 8)>>>((const float*)d_in[0]);
  nlstm_kernel<<<(B_ / 8) * CLUSTER, NTHR, sizeof(Smem)>>>(
      (const float*)d_in[1], (const float*)d_in[2], (const float*)d_in[3],
      (const float*)d_in[4], (const float*)d_in[5], (const float*)d_in[6],
      (const float*)d_in[7], (const float*)d_in[8], (float*)d_out);
}

// round 8
// speedup vs baseline: 1.1610x; 1.1610x over previous
#include <cuda_runtime.h>
#include <cstdint>

#define B_ 128
#define I_ 64
#define S_ 2048
#define CLUSTER 8
#define NTHR 256

// scratch: x transposed to [t][b][i]
__device__ float g_xT[(size_t)S_ * B_ * I_];

struct Smem {
  float in[192][8];          // k<64: x_t ; 64..192: h (cluster-shared)
  float iin[256][8];         // k<128: x_in ; else h_in (cluster-shared)
  float partial[8][64][10];  // gemv k-split partials, padded (2-way not 8-way conflicts)
  float Wlin[8][129];
  float partialP[8][8][9];   // projection partials [kq][oo][row]
  float blin[8];
  unsigned long long mbar_iin;
  unsigned long long mbar_h;
};

__device__ __forceinline__ float tanh_ap(float x) {
  float y;
  asm("tanh.approx.f32 %0, %1;" : "=f"(y) : "f"(x));
  return y;
}
__device__ __forceinline__ float sigm_t(float x) {
  return fmaf(0.5f, tanh_ap(0.5f * x), 0.5f);
}
__device__ __forceinline__ void ffma2(unsigned long long& d, unsigned long long a,
                                      unsigned long long b) {
  asm("fma.rn.f32x2 %0, %1, %2, %0;" : "+l"(d) : "l"(a), "l"(b));
}
__device__ __forceinline__ unsigned long long dupf(float w) {
  unsigned long long r;
  asm("mov.b64 %0, {%1, %1};" : "=l"(r) : "f"(w));
  return r;
}
__device__ __forceinline__ uint32_t mapa_u32(uint32_t addr, uint32_t r) {
  uint32_t o;
  asm("mapa.shared::cluster.u32 %0, %1, %2;" : "=r"(o) : "r"(addr), "r"(r));
  return o;
}
__device__ __forceinline__ void stc128(uint32_t addr, float4 v) {
  asm volatile("st.shared::cluster.v4.f32 [%0], {%1,%2,%3,%4};" ::"r"(addr), "f"(v.x),
               "f"(v.y), "f"(v.z), "f"(v.w)
               : "memory");
}
__device__ __forceinline__ void arrive_remote(uint32_t local_mbar, uint32_t r) {
  uint32_t rem = mapa_u32(local_mbar, r);
  asm volatile("mbarrier.arrive.release.cluster.shared::cluster.b64 _, [%0];" ::"r"(rem)
               : "memory");
}
__device__ __forceinline__ void mbar_init(uint32_t mbar, uint32_t count) {
  asm volatile("mbarrier.init.shared.b64 [%0], %1;" ::"r"(mbar), "r"(count) : "memory");
}
__device__ __forceinline__ void wait_parity_cluster(uint32_t mbar, uint32_t parity) {
  asm volatile(
      "{\n\t.reg .pred P1;\n\t"
      "WL_%=:\n\t"
      "mbarrier.try_wait.parity.acquire.cluster.shared::cta.b64 P1, [%0], %1, 0x989680;\n\t"
      "@P1 bra.uni WD_%=;\n\t"
      "bra.uni WL_%=;\n\t"
      "WD_%=:\n\t}" ::"r"(mbar),
      "r"(parity)
      : "memory");
}
__device__ __forceinline__ void cluster_sync_() {
  asm volatile("barrier.cluster.arrive.aligned;" ::: "memory");
  asm volatile("barrier.cluster.wait.aligned;" ::: "memory");
}

__global__ void transpose_x(const float* __restrict__ x) {
  __shared__ float tile[32][33];
  int b = blockIdx.z;
  int i0 = blockIdx.y * 32;
  int t0 = blockIdx.x * 32;
  int tx = threadIdx.x, ty = threadIdx.y;
#pragma unroll
  for (int j = 0; j < 32; j += 8)
    tile[ty + j][tx] = x[(size_t)b * (I_ * S_) + (size_t)(i0 + ty + j) * S_ + t0 + tx];
  __syncthreads();
#pragma unroll
  for (int j = 0; j < 32; j += 8)
    g_xT[(size_t)(t0 + ty + j) * (B_ * I_) + b * I_ + i0 + tx] = tile[tx][ty + j];
}

// projection partial on threads 128..255 (4 slots each)
__device__ __forceinline__ void proj_partial4(Smem& sm, int tid) {
#pragma unroll
  for (int s = 0; s < 4; ++s) {
    int slot = (tid - 128) + 128 * s;
    int kq = slot >> 6, oo = (slot >> 3) & 7, row = slot & 7;
    int k0 = kq * 16;
    float pa = 0.f;
#pragma unroll
    for (int kk = 0; kk < 16; ++kk) pa += sm.Wlin[oo][k0 + kk] * sm.in[64 + k0 + kk][row];
    sm.partialP[kq][oo][row] = pa;
  }
}
__device__ __forceinline__ void proj_reduce_stg(Smem& sm, int ltid, int tout, int rank, int b0,
                                                float* __restrict__ out) {
  int row = ltid & 7, oo = ltid >> 3;
  float s = sm.blin[oo];
#pragma unroll
  for (int kq = 0; kq < 8; ++kq) s += sm.partialP[kq][oo][row];
  out[((size_t)(b0 + row) * S_ + tout) * 64 + rank * 8 + oo] = s;
}

__global__ void __launch_bounds__(NTHR, 1) __cluster_dims__(CLUSTER, 1, 1)
nlstm_kernel(const float* __restrict__ Wx_out, const float* __restrict__ Wh_out,
             const float* __restrict__ b_out, const float* __restrict__ Wx_in,
             const float* __restrict__ Wh_in, const float* __restrict__ b_in,
             const float* __restrict__ W_lin, const float* __restrict__ b_lin,
             float* __restrict__ out) {
  extern __shared__ __align__(16) char smem_raw[];
  Smem& sm = *reinterpret_cast<Smem*>(smem_raw);
  const int tid = threadIdx.x;
  const int warp = tid >> 5, lane = tid & 31;
  const int rank = blockIdx.x & (CLUSTER - 1);
  const int b0 = (blockIdx.x >> 3) * 8;

  // ---- init ----
  if (tid < 8) sm.blin[tid] = b_lin[rank * 8 + tid];
  for (int idx = tid; idx < 8 * 128; idx += NTHR)
    sm.Wlin[idx >> 7][idx & 127] = W_lin[(rank * 8 + (idx >> 7)) * 128 + (idx & 127)];
  for (int idx = tid; idx < 128 * 8; idx += NTHR) sm.in[64 + (idx >> 3)][idx & 7] = 0.f;
  for (int idx = tid; idx < 512; idx += NTHR)  // stage x(0)
    sm.in[idx & 63][idx >> 6] = g_xT[(size_t)(b0 + (idx >> 6)) * I_ + (idx & 63)];
  const uint32_t mb_iin = (uint32_t)__cvta_generic_to_shared(&sm.mbar_iin);
  const uint32_t mb_h = (uint32_t)__cvta_generic_to_shared(&sm.mbar_h);
  if (tid == 0) {
    mbar_init(mb_iin, CLUSTER);  // one arrive per CTA (tid<8 -> one per target rank)
    mbar_init(mb_h, CLUSTER);
  }
  __syncthreads();
  cluster_sync_();

  // ---- register weights: warp = k-split (8), lane covers cols (lane, lane+32) ----
  float wOx[2][8], wOh[2][16], wI[2][32];
#pragma unroll
  for (int cg = 0; cg < 2; ++cg) {
    int c = cg * 32 + lane;
    int gcol = ((c >> 4) << 7) + (rank << 4) + (c & 15);
#pragma unroll
    for (int kk = 0; kk < 8; ++kk) wOx[cg][kk] = Wx_out[(warp * 8 + kk) * 512 + gcol];
#pragma unroll
    for (int kk = 0; kk < 16; ++kk) wOh[cg][kk] = Wh_out[(warp * 16 + kk) * 512 + gcol];
#pragma unroll
    for (int kk = 0; kk < 32; ++kk) {
      int k = warp * 32 + kk;
      wI[cg][kk] = (k < 128) ? Wx_in[k * 512 + gcol] : Wh_in[(k - 128) * 512 + gcol];
    }
  }
  // bias regs for reduce threads (tid<128): jj = tid>>3
  float boR[4], biR[4];
  {
    int jj = (tid & 127) >> 3;
#pragma unroll
    for (int g = 0; g < 4; ++g) {
      int gcol = g * 128 + rank * 16 + jj;
      boR[g] = b_out[gcol];
      biR[g] = b_in[gcol];
    }
  }

  const uint32_t iin_base = (uint32_t)__cvta_generic_to_shared(&sm.iin[0][0]);
  const uint32_t in_base = (uint32_t)__cvta_generic_to_shared(&sm.in[0][0]);

  float c_reg = 0.f, cn_reg = 0.f, o_save = 0.f;
  float4 xpf = make_float4(0.f, 0.f, 0.f, 0.f);

#pragma unroll 1
  for (int t = 0; t < S_; ++t) {
    // x(t+1) prefetch (warps 4-7): 128 threads x float4 = 512 floats
    if (tid >= 128 && t + 1 < S_)
      xpf = *reinterpret_cast<const float4*>(
          &g_xT[(size_t)(t + 1) * (B_ * I_) + b0 * I_ + (tid - 128) * 4]);

    // ---- P1: outer gemv ----
    unsigned long long a00 = 0, a01 = 0, a02 = 0, a03 = 0;
    unsigned long long a10 = 0, a11 = 0, a12 = 0, a13 = 0;
    {
      const float* up = &sm.in[warp * 8][0];
#pragma unroll
      for (int kk = 0; kk < 8; ++kk) {
        ulonglong2 u01 = *reinterpret_cast<const ulonglong2*>(up + kk * 8);
        ulonglong2 u23 = *reinterpret_cast<const ulonglong2*>(up + kk * 8 + 4);
        unsigned long long w0 = dupf(wOx[0][kk]);
        ffma2(a00, w0, u01.x);
        ffma2(a01, w0, u01.y);
        ffma2(a02, w0, u23.x);
        ffma2(a03, w0, u23.y);
        unsigned long long w1 = dupf(wOx[1][kk]);
        ffma2(a10, w1, u01.x);
        ffma2(a11, w1, u01.y);
        ffma2(a12, w1, u23.x);
        ffma2(a13, w1, u23.y);
      }
    }
    if (t != 0) wait_parity_cluster(mb_h, (t - 1) & 1);
    {
      const float* up = &sm.in[64 + warp * 16][0];
#pragma unroll
      for (int kk = 0; kk < 16; ++kk) {
        ulonglong2 u01 = *reinterpret_cast<const ulonglong2*>(up + kk * 8);
        ulonglong2 u23 = *reinterpret_cast<const ulonglong2*>(up + kk * 8 + 4);
        unsigned long long w0 = dupf(wOh[0][kk]);
        ffma2(a00, w0, u01.x);
        ffma2(a01, w0, u01.y);
        ffma2(a02, w0, u23.x);
        ffma2(a03, w0, u23.y);
        unsigned long long w1 = dupf(wOh[1][kk]);
        ffma2(a10, w1, u01.x);
        ffma2(a11, w1, u01.y);
        ffma2(a12, w1, u23.x);
        ffma2(a13, w1, u23.y);
      }
    }
    {
      unsigned long long* p = reinterpret_cast<unsigned long long*>(&sm.partial[warp][lane][0]);
      p[0] = a00;
      p[1] = a01;
      p[2] = a02;
      p[3] = a03;
      unsigned long long* q =
          reinterpret_cast<unsigned long long*>(&sm.partial[warp][32 + lane][0]);
      q[0] = a10;
      q[1] = a11;
      q[2] = a12;
      q[3] = a13;
    }
    __syncthreads();  // A

    // ---- P2: reduce/combine + fused iin bcast (w0-3) | proj partial (w4-7) ----
    if (tid < 128) {
      int jj = tid >> 3, row = tid & 7;
      float s0 = boR[0], s1 = boR[1], s2 = boR[2], s3 = boR[3];
#pragma unroll
      for (int ks = 0; ks < 8; ++ks) {
        s0 += sm.partial[ks][jj][row];
        s1 += sm.partial[ks][16 + jj][row];
        s2 += sm.partial[ks][32 + jj][row];
        s3 += sm.partial[ks][48 + jj][row];
      }
      float iv = sigm_t(s0), fv = sigm_t(s1);
      o_save = sigm_t(s2);
      float gv = tanh_ap(s3);
      sm.iin[rank * 16 + jj][row] = iv * gv;           // x_in, local
      sm.iin[128 + rank * 16 + jj][row] = fv * c_reg;  // h_in, local
      __syncwarp();
      // warp w owns jj rows [w*4, w*4+4): bcast 128B x 2 halves to 8 ranks
      {
        int r = lane >> 2, cb = lane & 3;
        uint32_t slice = (uint32_t)(rank * 16 + warp * 4) * 32;
#pragma unroll
        for (int cc = 0; cc < 2; ++cc) {
          int c = cb + cc * 4;
          uint32_t off = slice + (uint32_t)c * 16;
          float4 vx = *reinterpret_cast<const float4*>(
              &sm.iin[rank * 16 + warp * 4 + (c >> 1)][(c & 1) * 4]);
          float4 vh = *reinterpret_cast<const float4*>(
              &sm.iin[128 + rank * 16 + warp * 4 + (c >> 1)][(c & 1) * 4]);
          stc128(mapa_u32(iin_base + off, r), vx);
          stc128(mapa_u32(iin_base + 4096 + off, r), vh);
        }
      }
    } else {
      if (t > 0) proj_partial4(sm, tid);
    }
    __syncthreads();  // B (drains cluster stores; R4-proven arrive discipline below)
    if (tid < 8) arrive_remote(mb_iin, tid);
    wait_parity_cluster(mb_iin, t & 1);

    // ---- P3: inner gemv (k 0..255) ----
    {
      unsigned long long b00 = 0, b01 = 0, b02 = 0, b03 = 0;
      unsigned long long b10 = 0, b11 = 0, b12 = 0, b13 = 0;
      const float* up = &sm.iin[warp * 32][0];
#pragma unroll
      for (int kk = 0; kk < 32; ++kk) {
        ulonglong2 u01 = *reinterpret_cast<const ulonglong2*>(up + kk * 8);
        ulonglong2 u23 = *reinterpret_cast<const ulonglong2*>(up + kk * 8 + 4);
        unsigned long long w0 = dupf(wI[0][kk]);
        ffma2(b00, w0, u01.x);
        ffma2(b01, w0, u01.y);
        ffma2(b02, w0, u23.x);
        ffma2(b03, w0, u23.y);
        unsigned long long w1 = dupf(wI[1][kk]);
        ffma2(b10, w1, u01.x);
        ffma2(b11, w1, u01.y);
        ffma2(b12, w1, u23.x);
        ffma2(b13, w1, u23.y);
      }
      unsigned long long* p = reinterpret_cast<unsigned long long*>(&sm.partial[warp][lane][0]);
      p[0] = b00;
      p[1] = b01;
      p[2] = b02;
      p[3] = b03;
      unsigned long long* q =
          reinterpret_cast<unsigned long long*>(&sm.partial[warp][32 + lane][0]);
      q[0] = b10;
      q[1] = b11;
      q[2] = b12;
      q[3] = b13;
    }
    __syncthreads();  // C

    // ---- P4: inner reduce/state + fused h bcast (w0-3) | proj reduce+STG, x stage (w4-7) ----
    if (tid < 128) {
      int jj = tid >> 3, row = tid & 7;
      float s0 = biR[0], s1 = biR[1], s2 = biR[2], s3 = biR[3];
#pragma unroll
      for (int ks = 0; ks < 8; ++ks) {
        s0 += sm.partial[ks][jj][row];
        s1 += sm.partial[ks][16 + jj][row];
        s2 += sm.partial[ks][32 + jj][row];
        s3 += sm.partial[ks][48 + jj][row];
      }
      float ii = sigm_t(s0), ff = sigm_t(s1), o2 = sigm_t(s2), gg = tanh_ap(s3);
      cn_reg = ff * cn_reg + ii * gg;
      c_reg = o2 * tanh_ap(cn_reg);
      sm.in[64 + rank * 16 + jj][row] = o_save * tanh_ap(c_reg);  // h, local
      __syncwarp();
      {  // bcast warp's 128B h slice to 8 ranks: 64 chunk-sends / 32 lanes = 2
        int r = lane >> 2, cb = lane & 3;
        uint32_t slice = (uint32_t)(64 + rank * 16 + warp * 4) * 32;
#pragma unroll
        for (int cc = 0; cc < 2; ++cc) {
          int c = cb + cc * 4;
          uint32_t off = slice + (uint32_t)c * 16;
          float4 v = *reinterpret_cast<const float4*>(
              &sm.in[64 + rank * 16 + warp * 4 + (c >> 1)][(c & 1) * 4]);
          stc128(mapa_u32(in_base + off, r), v);
        }
      }
    } else {
      if (t > 0 && tid < 192) proj_reduce_stg(sm, tid - 128, t - 1, rank, b0, out);
      if (t + 1 < S_) {
        int idx = (tid - 128) * 4;
        int row = idx >> 6, i = idx & 63;
        sm.in[i][row] = xpf.x;
        sm.in[i + 1][row] = xpf.y;
        sm.in[i + 2][row] = xpf.z;
        sm.in[i + 3][row] = xpf.w;
      }
    }
    __syncthreads();  // D
    if (tid < 8) arrive_remote(mb_h, tid);
  }

  // ---- epilogue: projection for t = S_-1 ----
  wait_parity_cluster(mb_h, (S_ - 1) & 1);
  if (tid >= 128) proj_partial4(sm, tid);
  __syncthreads();
  if (tid >= 128 && tid < 192) proj_reduce_stg(sm, tid - 128, S_ - 1, rank, b0, out);
}

extern "C" void kernel_launch(void* const* d_in, const int* in_sizes, int n_in,
                              void* d_out, int out_size) {
  (void)in_sizes;
  (void)n_in;
  (void)out_size;
  cudaFuncSetAttribute(nlstm_kernel, cudaFuncAttributeMaxDynamicSharedMemorySize,
                       (int)sizeof(Smem));
  transpose_x<<<dim3(S_ / 32, I_ / 32, B_), dim3(32, 8)>>>((const float*)d_in[0]);
  nlstm_kernel<<<(B_ / 8) * CLUSTER, NTHR, sizeof(Smem)>>>(
      (const float*)d_in[1], (const float*)d_in[2], (const float*)d_in[3],
      (const float*)d_in[4], (const float*)d_in[5], (const float*)d_in[6],
      (const float*)d_in[7], (const float*)d_in[8], (float*)d_out);
}

// round 10
// speedup vs baseline: 1.8083x; 1.5574x over previous
#include <cuda_runtime.h>
#include <cstdint>

#define B_ 128
#define I_ 64
#define S_ 2048
#define CLUSTER 8
#define NTHR 256

// scratch: x transposed to [t][b][i]
__device__ float g_xT[(size_t)S_ * B_ * I_];

struct Smem {
  float in[192][8];          // k<64: x_t ; 64..192: h (cluster-shared)
  float iin[256][8];         // k<128: x_in ; else h_in (cluster-shared)
  float partial[8][64][10];  // gemv k-split partials, padded (2-way not 8-way conflicts)
  float Wlin[8][129];
  float partialP[8][8][9];   // projection partials [kq][oo][row]
  float blin[8];
  unsigned long long mbar_iin;
  unsigned long long mbar_h;
};

__device__ __forceinline__ float tanh_ap(float x) {
  float y;
  asm("tanh.approx.f32 %0, %1;" : "=f"(y) : "f"(x));
  return y;
}
__device__ __forceinline__ float sigm_t(float x) {
  return fmaf(0.5f, tanh_ap(0.5f * x), 0.5f);
}
__device__ __forceinline__ void ffma2(unsigned long long& d, unsigned long long a,
                                      unsigned long long b) {
  asm("fma.rn.f32x2 %0, %1, %2, %0;" : "+l"(d) : "l"(a), "l"(b));
}
__device__ __forceinline__ unsigned long long dupf(float w) {
  unsigned long long r;
  asm("mov.b64 %0, {%1, %1};" : "=l"(r) : "f"(w));
  return r;
}
__device__ __forceinline__ uint32_t mapa_u32(uint32_t addr, uint32_t r) {
  uint32_t o;
  asm("mapa.shared::cluster.u32 %0, %1, %2;" : "=r"(o) : "r"(addr), "r"(r));
  return o;
}
__device__ __forceinline__ void stc128(uint32_t addr, float4 v) {
  asm volatile("st.shared::cluster.v4.f32 [%0], {%1,%2,%3,%4};" ::"r"(addr), "f"(v.x),
               "f"(v.y), "f"(v.z), "f"(v.w)
               : "memory");
}
__device__ __forceinline__ void arrive_remote(uint32_t local_mbar, uint32_t r) {
  uint32_t rem = mapa_u32(local_mbar, r);
  asm volatile("mbarrier.arrive.release.cluster.shared::cluster.b64 _, [%0];" ::"r"(rem)
               : "memory");
}
__device__ __forceinline__ void mbar_init(uint32_t mbar, uint32_t count) {
  asm volatile("mbarrier.init.shared.b64 [%0], %1;" ::"r"(mbar), "r"(count) : "memory");
}
__device__ __forceinline__ void wait_parity_cluster(uint32_t mbar, uint32_t parity) {
  asm volatile(
      "{\n\t.reg .pred P1;\n\t"
      "WL_%=:\n\t"
      "mbarrier.try_wait.parity.acquire.cluster.shared::cta.b64 P1, [%0], %1, 0x989680;\n\t"
      "@P1 bra.uni WD_%=;\n\t"
      "bra.uni WL_%=;\n\t"
      "WD_%=:\n\t}" ::"r"(mbar),
      "r"(parity)
      : "memory");
}
__device__ __forceinline__ void cluster_sync_() {
  asm volatile("barrier.cluster.arrive.aligned;" ::: "memory");
  asm volatile("barrier.cluster.wait.aligned;" ::: "memory");
}

__global__ void transpose_x(const float* __restrict__ x) {
  __shared__ float tile[32][33];
  int b = blockIdx.z;
  int i0 = blockIdx.y * 32;
  int t0 = blockIdx.x * 32;
  int tx = threadIdx.x, ty = threadIdx.y;
#pragma unroll
  for (int j = 0; j < 32; j += 8)
    tile[ty + j][tx] = x[(size_t)b * (I_ * S_) + (size_t)(i0 + ty + j) * S_ + t0 + tx];
  __syncthreads();
#pragma unroll
  for (int j = 0; j < 32; j += 8)
    g_xT[(size_t)(t0 + ty + j) * (B_ * I_) + b * I_ + i0 + tx] = tile[tx][ty + j];
}

// projection partial on threads 128..255 (4 slots each)
__device__ __forceinline__ void proj_partial4(Smem& sm, int tid) {
#pragma unroll
  for (int s = 0; s < 4; ++s) {
    int slot = (tid - 128) + 128 * s;
    int kq = slot >> 6, oo = (slot >> 3) & 7, row = slot & 7;
    int k0 = kq * 16;
    float pa = 0.f;
#pragma unroll
    for (int kk = 0; kk < 16; ++kk) pa += sm.Wlin[oo][k0 + kk] * sm.in[64 + k0 + kk][row];
    sm.partialP[kq][oo][row] = pa;
  }
}
__device__ __forceinline__ void proj_reduce_stg(Smem& sm, int ltid, int tout, int rank, int b0,
                                                float* __restrict__ out) {
  int row = ltid & 7, oo = ltid >> 3;
  float s = sm.blin[oo];
#pragma unroll
  for (int kq = 0; kq < 8; ++kq) s += sm.partialP[kq][oo][row];
  out[((size_t)(b0 + row) * S_ + tout) * 64 + rank * 8 + oo] = s;
}

__global__ void __launch_bounds__(NTHR, 1) __cluster_dims__(CLUSTER, 1, 1)
nlstm_kernel(const float* __restrict__ Wx_out, const float* __restrict__ Wh_out,
             const float* __restrict__ b_out, const float* __restrict__ Wx_in,
             const float* __restrict__ Wh_in, const float* __restrict__ b_in,
             const float* __restrict__ W_lin, const float* __restrict__ b_lin,
             float* __restrict__ out) {
  extern __shared__ __align__(16) char smem_raw[];
  Smem& sm = *reinterpret_cast<Smem*>(smem_raw);
  const int tid = threadIdx.x;
  const int warp = tid >> 5, lane = tid & 31;
  const int rank = blockIdx.x & (CLUSTER - 1);
  const int b0 = (blockIdx.x >> 3) * 8;

  // ---- init ----
  if (tid < 8) sm.blin[tid] = b_lin[rank * 8 + tid];
  for (int idx = tid; idx < 8 * 128; idx += NTHR)
    sm.Wlin[idx >> 7][idx & 127] = W_lin[(rank * 8 + (idx >> 7)) * 128 + (idx & 127)];
  for (int idx = tid; idx < 128 * 8; idx += NTHR) sm.in[64 + (idx >> 3)][idx & 7] = 0.f;
  for (int idx = tid; idx < 512; idx += NTHR)  // stage x(0)
    sm.in[idx & 63][idx >> 6] = g_xT[(size_t)(b0 + (idx >> 6)) * I_ + (idx & 63)];
  const uint32_t mb_iin = (uint32_t)__cvta_generic_to_shared(&sm.mbar_iin);
  const uint32_t mb_h = (uint32_t)__cvta_generic_to_shared(&sm.mbar_h);
  if (tid == 0) {
    mbar_init(mb_iin, CLUSTER);  // one arrive per CTA (tid<8 -> one per target rank)
    mbar_init(mb_h, CLUSTER);
  }
  __syncthreads();
  cluster_sync_();

  // ---- register weights: warp = k-split (8), lane covers cols (lane, lane+32) ----
  float wOx[2][8], wOh[2][16], wI[2][32];
#pragma unroll
  for (int cg = 0; cg < 2; ++cg) {
    int c = cg * 32 + lane;
    int gcol = ((c >> 4) << 7) + (rank << 4) + (c & 15);
#pragma unroll
    for (int kk = 0; kk < 8; ++kk) wOx[cg][kk] = Wx_out[(warp * 8 + kk) * 512 + gcol];
#pragma unroll
    for (int kk = 0; kk < 16; ++kk) wOh[cg][kk] = Wh_out[(warp * 16 + kk) * 512 + gcol];
#pragma unroll
    for (int kk = 0; kk < 32; ++kk) {
      int k = warp * 32 + kk;
      wI[cg][kk] = (k < 128) ? Wx_in[k * 512 + gcol] : Wh_in[(k - 128) * 512 + gcol];
    }
  }
  // bias regs for reduce threads (tid<128): jj = tid>>3
  float boR[4], biR[4];
  {
    int jj = (tid & 127) >> 3;
#pragma unroll
    for (int g = 0; g < 4; ++g) {
      int gcol = g * 128 + rank * 16 + jj;
      boR[g] = b_out[gcol];
      biR[g] = b_in[gcol];
    }
  }

  const uint32_t iin_base = (uint32_t)__cvta_generic_to_shared(&sm.iin[0][0]);
  const uint32_t in_base = (uint32_t)__cvta_generic_to_shared(&sm.in[0][0]);

  float c_reg = 0.f, cn_reg = 0.f, o_save = 0.f;
  float4 xpf = make_float4(0.f, 0.f, 0.f, 0.f);

#pragma unroll 1
  for (int t = 0; t < S_; ++t) {
    // x(t+1) prefetch (warps 4-7): 128 threads x float4 = 512 floats
    if (tid >= 128 && t + 1 < S_)
      xpf = *reinterpret_cast<const float4*>(
          &g_xT[(size_t)(t + 1) * (B_ * I_) + b0 * I_ + (tid - 128) * 4]);

    // ---- P1: outer gemv ----
    unsigned long long a00 = 0, a01 = 0, a02 = 0, a03 = 0;
    unsigned long long a10 = 0, a11 = 0, a12 = 0, a13 = 0;
    {
      const float* up = &sm.in[warp * 8][0];
#pragma unroll
      for (int kk = 0; kk < 8; ++kk) {
        ulonglong2 u01 = *reinterpret_cast<const ulonglong2*>(up + kk * 8);
        ulonglong2 u23 = *reinterpret_cast<const ulonglong2*>(up + kk * 8 + 4);
        unsigned long long w0 = dupf(wOx[0][kk]);
        ffma2(a00, w0, u01.x);
        ffma2(a01, w0, u01.y);
        ffma2(a02, w0, u23.x);
        ffma2(a03, w0, u23.y);
        unsigned long long w1 = dupf(wOx[1][kk]);
        ffma2(a10, w1, u01.x);
        ffma2(a11, w1, u01.y);
        ffma2(a12, w1, u23.x);
        ffma2(a13, w1, u23.y);
      }
    }
    if (t != 0) wait_parity_cluster(mb_h, (t - 1) & 1);
    {
      const float* up = &sm.in[64 + warp * 16][0];
#pragma unroll
      for (int kk = 0; kk < 16; ++kk) {
        ulonglong2 u01 = *reinterpret_cast<const ulonglong2*>(up + kk * 8);
        ulonglong2 u23 = *reinterpret_cast<const ulonglong2*>(up + kk * 8 + 4);
        unsigned long long w0 = dupf(wOh[0][kk]);
        ffma2(a00, w0, u01.x);
        ffma2(a01, w0, u01.y);
        ffma2(a02, w0, u23.x);
        ffma2(a03, w0, u23.y);
        unsigned long long w1 = dupf(wOh[1][kk]);
        ffma2(a10, w1, u01.x);
        ffma2(a11, w1, u01.y);
        ffma2(a12, w1, u23.x);
        ffma2(a13, w1, u23.y);
      }
    }
    {
      unsigned long long* p = reinterpret_cast<unsigned long long*>(&sm.partial[warp][lane][0]);
      p[0] = a00;
      p[1] = a01;
      p[2] = a02;
      p[3] = a03;
      unsigned long long* q =
          reinterpret_cast<unsigned long long*>(&sm.partial[warp][32 + lane][0]);
      q[0] = a10;
      q[1] = a11;
      q[2] = a12;
      q[3] = a13;
    }
    __syncthreads();  // A

    // ---- P2: reduce/combine + fused RANK-UNIFORM iin bcast (w0-3) | proj (w4-7) ----
    if (tid < 128) {
      int jj = tid >> 3, row = tid & 7;
      float s0 = boR[0], s1 = boR[1], s2 = boR[2], s3 = boR[3];
#pragma unroll
      for (int ks = 0; ks < 8; ++ks) {
        s0 += sm.partial[ks][jj][row];
        s1 += sm.partial[ks][16 + jj][row];
        s2 += sm.partial[ks][32 + jj][row];
        s3 += sm.partial[ks][48 + jj][row];
      }
      float iv = sigm_t(s0), fv = sigm_t(s1);
      o_save = sigm_t(s2);
      float gv = tanh_ap(s3);
      sm.iin[rank * 16 + jj][row] = iv * gv;           // x_in, local
      sm.iin[128 + rank * 16 + jj][row] = fv * c_reg;  // h_in, local
      __syncwarp();
      // warp w owns jj rows [w*4, w*4+4): 2 arrays x 128B = 16 chunks; 16 lanes,
      // each sends its chunk to all 8 ranks (uniform rank per instruction)
      if (lane < 16) {
        int half = lane >> 3, ch = lane & 7;
        uint32_t byte_off = (uint32_t)((half * 128 + rank * 16 + warp * 4) * 32 + ch * 16);
        float4 v = *reinterpret_cast<const float4*>((const char*)&sm.iin[0][0] + byte_off);
#pragma unroll
        for (int r = 0; r < CLUSTER; ++r) stc128(mapa_u32(iin_base + byte_off, r), v);
      }
    } else {
      if (t > 0) proj_partial4(sm, tid);
    }
    __syncthreads();  // B (drains cluster stores; R4-proven arrive discipline below)
    if (tid < 8) arrive_remote(mb_iin, tid);
    wait_parity_cluster(mb_iin, t & 1);

    // ---- P3: inner gemv (k 0..255) ----
    {
      unsigned long long b00 = 0, b01 = 0, b02 = 0, b03 = 0;
      unsigned long long b10 = 0, b11 = 0, b12 = 0, b13 = 0;
      const float* up = &sm.iin[warp * 32][0];
#pragma unroll
      for (int kk = 0; kk < 32; ++kk) {
        ulonglong2 u01 = *reinterpret_cast<const ulonglong2*>(up + kk * 8);
        ulonglong2 u23 = *reinterpret_cast<const ulonglong2*>(up + kk * 8 + 4);
        unsigned long long w0 = dupf(wI[0][kk]);
        ffma2(b00, w0, u01.x);
        ffma2(b01, w0, u01.y);
        ffma2(b02, w0, u23.x);
        ffma2(b03, w0, u23.y);
        unsigned long long w1 = dupf(wI[1][kk]);
        ffma2(b10, w1, u01.x);
        ffma2(b11, w1, u01.y);
        ffma2(b12, w1, u23.x);
        ffma2(b13, w1, u23.y);
      }
      unsigned long long* p = reinterpret_cast<unsigned long long*>(&sm.partial[warp][lane][0]);
      p[0] = b00;
      p[1] = b01;
      p[2] = b02;
      p[3] = b03;
      unsigned long long* q =
          reinterpret_cast<unsigned long long*>(&sm.partial[warp][32 + lane][0]);
      q[0] = b10;
      q[1] = b11;
      q[2] = b12;
      q[3] = b13;
    }
    __syncthreads();  // C

    // ---- P4: inner reduce/state + fused RANK-UNIFORM h bcast (w0-3) | rest (w4-7) ----
    if (tid < 128) {
      int jj = tid >> 3, row = tid & 7;
      float s0 = biR[0], s1 = biR[1], s2 = biR[2], s3 = biR[3];
#pragma unroll
      for (int ks = 0; ks < 8; ++ks) {
        s0 += sm.partial[ks][jj][row];
        s1 += sm.partial[ks][16 + jj][row];
        s2 += sm.partial[ks][32 + jj][row];
        s3 += sm.partial[ks][48 + jj][row];
      }
      float ii = sigm_t(s0), ff = sigm_t(s1), o2 = sigm_t(s2), gg = tanh_ap(s3);
      cn_reg = ff * cn_reg + ii * gg;
      c_reg = o2 * tanh_ap(cn_reg);
      sm.in[64 + rank * 16 + jj][row] = o_save * tanh_ap(c_reg);  // h, local
      __syncwarp();
      // warp's 128B h slice = 8 chunks; 8 lanes, each to all 8 ranks (uniform)
      if (lane < 8) {
        uint32_t byte_off = (uint32_t)((64 + rank * 16 + warp * 4) * 32 + lane * 16);
        float4 v = *reinterpret_cast<const float4*>((const char*)&sm.in[0][0] + byte_off);
#pragma unroll
        for (int r = 0; r < CLUSTER; ++r) stc128(mapa_u32(in_base + byte_off, r), v);
      }
    } else {
      if (t > 0 && tid < 192) proj_reduce_stg(sm, tid - 128, t - 1, rank, b0, out);
      if (t + 1 < S_) {
        int idx = (tid - 128) * 4;
        int row = idx >> 6, i = idx & 63;
        sm.in[i][row] = xpf.x;
        sm.in[i + 1][row] = xpf.y;
        sm.in[i + 2][row] = xpf.z;
        sm.in[i + 3][row] = xpf.w;
      }
    }
    __syncthreads();  // D
    if (tid < 8) arrive_remote(mb_h, tid);
  }

  // ---- epilogue: projection for t = S_-1 ----
  wait_parity_cluster(mb_h, (S_ - 1) & 1);
  if (tid >= 128) proj_partial4(sm, tid);
  __syncthreads();
  if (tid >= 128 && tid < 192) proj_reduce_stg(sm, tid - 128, S_ - 1, rank, b0, out);
}

extern "C" void kernel_launch(void* const* d_in, const int* in_sizes, int n_in,
                              void* d_out, int out_size) {
  (void)in_sizes;
  (void)n_in;
  (void)out_size;
  cudaFuncSetAttribute(nlstm_kernel, cudaFuncAttributeMaxDynamicSharedMemorySize,
                       (int)sizeof(Smem));
  transpose_x<<<dim3(S_ / 32, I_ / 32, B_), dim3(32, 8)>>>((const float*)d_in[0]);
  nlstm_kernel<<<(B_ / 8) * CLUSTER, NTHR, sizeof(Smem)>>>(
      (const float*)d_in[1], (const float*)d_in[2], (const float*)d_in[3],
      (const float*)d_in[4], (const float*)d_in[5], (const float*)d_in[6],
      (const float*)d_in[7], (const float*)d_in[8], (float*)d_out);
}